// round 3
// baseline (speedup 1.0000x reference)
#include <cuda_runtime.h>
#include <cuda_bf16.h>

#define HH 1024
#define WW 1024

static constexpr int NBLOCKS  = 1184;
static constexpr int NTHREADS = 256;

__device__ float        g_part[NBLOCKS];
__device__ unsigned int g_count = 0;

typedef unsigned long long ull;

__device__ __forceinline__ ull pk(float lo, float hi) {
    ull r; asm("mov.b64 %0, {%1, %2};" : "=l"(r) : "f"(lo), "f"(hi)); return r;
}
__device__ __forceinline__ ull sub2(ull a, ull b) {
    ull r; asm("sub.rn.f32x2 %0, %1, %2;" : "=l"(r) : "l"(a), "l"(b)); return r;
}
__device__ __forceinline__ ull fma2(ull a, ull b, ull c) {
    ull r; asm("fma.rn.f32x2 %0, %1, %2, %3;" : "=l"(r) : "l"(a), "l"(b), "l"(c)); return r;
}
__device__ __forceinline__ void unpk(ull v, float& lo, float& hi) {
    asm("mov.b64 {%0, %1}, %2;" : "=f"(lo), "=f"(hi) : "l"(v));
}

// Directed decomposition: total = 2 * (S_directed + S_edge)
__device__ __forceinline__ void quad_fast(const float4 c, const float4 b,
                                          float bl, float cr, float br, ull& acc2) {
    const ull vp01 = pk(c.x, c.y), vp23 = pk(c.z, c.w);
    ull d;
    d = sub2(vp01, pk(c.y, c.z)); acc2 = fma2(d, d, acc2);   // right
    d = sub2(vp23, pk(c.w, cr));  acc2 = fma2(d, d, acc2);
    d = sub2(vp01, pk(b.x, b.y)); acc2 = fma2(d, d, acc2);   // down
    d = sub2(vp23, pk(b.z, b.w)); acc2 = fma2(d, d, acc2);
    const ull m12 = pk(b.y, b.z);
    d = sub2(vp01, pk(bl, b.x));  acc2 = fma2(d, d, acc2);   // down-left
    d = sub2(vp23, m12);          acc2 = fma2(d, d, acc2);
    d = sub2(vp01, m12);          acc2 = fma2(d, d, acc2);   // down-right
    d = sub2(vp23, pk(b.w, br));  acc2 = fma2(d, d, acc2);
}

// Scalar clamped boundary path for one pixel (group-local index k, global col j)
__device__ __forceinline__ void pix_slow(const float* __restrict__ cur,
                                         const float* __restrict__ nxt,
                                         int k, int j, bool hasD, bool hRow,
                                         float& accs) {
    const float v = cur[k];
    const bool hasR = (j + 1 <= WW - 1);
    if (hasR) {
        const float d = v - cur[k + 1];
        const float q = d * d;
        accs += hRow ? (q + q) : q;
    }
    if (hasD) {
        const bool vCol = (j == 0) || (j == WW - 1);
        float d = v - nxt[k];
        float q = d * d;
        accs += vCol ? (q + q) : q;
        if (j > 0) { d = v - nxt[k - 1]; accs += d * d; }
        if (hasR)  { d = v - nxt[k + 1]; accs += d * d; }
    }
}

__global__ __launch_bounds__(NTHREADS)
void lap_kernel(const float* __restrict__ f, float* __restrict__ out, int total_g) {
    ull   acc2 = 0;
    float accs = 0.0f;
    const int stride = gridDim.x * blockDim.x;

    // One work item = 8 consecutive float4 quads = 32 pixels (128B-aligned strip)
    for (int t = blockIdx.x * blockDim.x + threadIdx.x; t < total_g; t += stride) {
        const int rq = t >> 5;          // global row (plane*H + i); 32 groups/row
        const int gq = t & 31;          // group within row
        const int i  = rq & (HH - 1);
        const float* __restrict__ base = f + ((size_t)(rq >> 10) << 20);
        const float* __restrict__ cur  = base + ((size_t)i << 10) + (gq << 5);
        const float* __restrict__ nxt  = cur + WW;

        if (i >= 1 && i <= HH - 2) {
            if (gq >= 1 && gq <= 30) {
                // ---- fast strip: halos carried in registers ----
                float4 c0 = *(const float4*)cur;
                float4 b0 = *(const float4*)nxt;
                float  bl = nxt[-1];
                #pragma unroll
                for (int q = 0; q < 8; q++) {
                    float4 c1, b1; float crx, brx;
                    if (q < 7) {
                        c1  = *(const float4*)(cur + 4 * (q + 1));
                        b1  = *(const float4*)(nxt + 4 * (q + 1));
                        crx = c1.x; brx = b1.x;
                    } else {
                        crx = cur[32]; brx = nxt[32];
                        c1 = c0; b1 = b0;   // dead
                    }
                    quad_fast(c0, b0, bl, crx, brx, acc2);
                    bl = b0.w; c0 = c1; b0 = b1;
                }
            } else {
                // ---- edge group (contains col 0 or col W-1): per-quad ----
                #pragma unroll
                for (int q = 0; q < 8; q++) {
                    const int j0 = (gq << 5) + (q << 2);
                    if (j0 >= 4 && j0 <= WW - 8) {
                        const float4 c = *(const float4*)(cur + 4 * q);
                        const float4 b = *(const float4*)(nxt + 4 * q);
                        quad_fast(c, b, nxt[4 * q - 1], cur[4 * q + 4], nxt[4 * q + 4], acc2);
                    } else {
                        #pragma unroll
                        for (int k = 0; k < 4; k++)
                            pix_slow(cur, nxt, 4 * q + k, j0 + k, true, false, accs);
                    }
                }
            }
        } else {
            // ---- boundary row (i==0 or i==H-1): scalar clamped path ----
            const bool hasD = (i == 0);
            #pragma unroll 4
            for (int k = 0; k < 32; k++)
                pix_slow(cur, nxt, k, (gq << 5) + k, hasD, true, accs);
        }
    }

    float lo, hi; unpk(acc2, lo, hi);
    float acc = accs + lo + hi;

    // ---- deterministic block reduction ----
    __shared__ float swarp[NTHREADS / 32];
    #pragma unroll
    for (int o = 16; o > 0; o >>= 1)
        acc += __shfl_down_sync(0xffffffffu, acc, o);
    if ((threadIdx.x & 31) == 0) swarp[threadIdx.x >> 5] = acc;
    __syncthreads();
    if (threadIdx.x < NTHREADS / 32) {
        float v = swarp[threadIdx.x];
        #pragma unroll
        for (int o = NTHREADS / 64; o > 0; o >>= 1)
            v += __shfl_down_sync(0xffu, v, o);
        if (threadIdx.x == 0) g_part[blockIdx.x] = v;
    }

    // ---- last-block final reduction ----
    __shared__ bool isLast;
    if (threadIdx.x == 0) {
        __threadfence();
        isLast = (atomicAdd(&g_count, 1u) == (unsigned)gridDim.x - 1u);
    }
    __syncthreads();
    if (isLast) {
        volatile float* gp = g_part;
        double v = 0.0;
        for (int idx = threadIdx.x; idx < NBLOCKS; idx += NTHREADS) v += (double)gp[idx];
        __shared__ double sd[NTHREADS];
        sd[threadIdx.x] = v;
        __syncthreads();
        #pragma unroll
        for (int o = NTHREADS / 2; o > 0; o >>= 1) {
            if (threadIdx.x < o) sd[threadIdx.x] += sd[threadIdx.x + o];
            __syncthreads();
        }
        if (threadIdx.x == 0) {
            out[0] = (float)(2.0 * sd[0]);
            g_count = 0;
        }
    }
}

extern "C" void kernel_launch(void* const* d_in, const int* in_sizes, int n_in,
                              void* d_out, int out_size) {
    const float* f = (const float*)d_in[0];
    const int n = in_sizes[0];
    const int total_g = n >> 5;   // 32 pixels per work item
    lap_kernel<<<NBLOCKS, NTHREADS>>>(f, (float*)d_out, total_g);
}

// round 5
// speedup vs baseline: 2.9128x; 2.9128x over previous
#include <cuda_runtime.h>
#include <cuda_bf16.h>

#define HH 1024
#define WW 1024

static constexpr int NBLOCKS  = 1184;
static constexpr int NTHREADS = 256;

__device__ float        g_part[NBLOCKS];
__device__ unsigned int g_count = 0;

typedef unsigned long long ull;

__device__ __forceinline__ ull pk(float lo, float hi) {
    ull r; asm("mov.b64 %0, {%1, %2};" : "=l"(r) : "f"(lo), "f"(hi)); return r;
}
__device__ __forceinline__ ull sub2(ull a, ull b) {
    ull r; asm("sub.rn.f32x2 %0, %1, %2;" : "=l"(r) : "l"(a), "l"(b)); return r;
}
__device__ __forceinline__ ull fma2(ull a, ull b, ull c) {
    ull r; asm("fma.rn.f32x2 %0, %1, %2, %3;" : "=l"(r) : "l"(a), "l"(b), "l"(c)); return r;
}
__device__ __forceinline__ void unpk(ull v, float& lo, float& hi) {
    asm("mov.b64 {%0, %1}, %2;" : "=f"(lo), "=f"(hi) : "l"(v));
}

// total = 2 * S, where S = directed sum {(0,1),(1,-1),(1,0),(1,1)} with
// edge duplicates realized purely by halo value substitution:
//   col 0   : bl := b.x   -> down-left term becomes the col-0 vertical dup
//   col W-1 : cr := c.w   -> right term vanishes
//             br := b.w   -> down-right term becomes the col-(W-1) vertical dup
//   row 0   : horizontal terms added once more (x2 total)
//   row H-1 : horizontal terms only, x2
__device__ __forceinline__ void quad_fast(const float4 c, const float4 b,
                                          float bl, float cr, float br, ull& acc2) {
    const ull vp01 = pk(c.x, c.y), vp23 = pk(c.z, c.w);
    ull d;
    d = sub2(vp01, pk(c.y, c.z)); acc2 = fma2(d, d, acc2);   // right
    d = sub2(vp23, pk(c.w, cr));  acc2 = fma2(d, d, acc2);
    d = sub2(vp01, pk(b.x, b.y)); acc2 = fma2(d, d, acc2);   // down
    d = sub2(vp23, pk(b.z, b.w)); acc2 = fma2(d, d, acc2);
    const ull m12 = pk(b.y, b.z);
    d = sub2(vp01, pk(bl, b.x));  acc2 = fma2(d, d, acc2);   // down-left
    d = sub2(vp23, m12);          acc2 = fma2(d, d, acc2);
    d = sub2(vp01, m12);          acc2 = fma2(d, d, acc2);   // down-right
    d = sub2(vp23, pk(b.w, br));  acc2 = fma2(d, d, acc2);
}

__global__ __launch_bounds__(NTHREADS)
void lap_kernel(const float* __restrict__ f, float* __restrict__ out, int total_q) {
    ull acc2 = 0;
    const int stride = gridDim.x * blockDim.x;
    const int lane = threadIdx.x & 31;

    // One work item = one float4 quad; warp = 32 adjacent quads = 128 contiguous
    // pixels of one row (256 quads/row, divisible by 32 -> warp never straddles rows).
    for (int t = blockIdx.x * blockDim.x + threadIdx.x; t < total_q; t += stride) {
        const int rq = t >> 8;            // plane*H + i
        const int jq = t & 255;           // quad within row
        const int i  = rq & (HH - 1);
        const float* __restrict__ cur = f + ((size_t)rq << 10);
        const int j0 = jq << 2;
        const bool firstq = (jq == 0);
        const bool lastq  = (jq == 255);

        if (i < HH - 1) {
            const float* __restrict__ nxt = cur + WW;
            const float4 c = *(const float4*)(cur + j0);
            const float4 b = *(const float4*)(nxt + j0);

            float cr = __shfl_down_sync(0xffffffffu, c.x, 1);
            float br = __shfl_down_sync(0xffffffffu, b.x, 1);
            float bl = __shfl_up_sync  (0xffffffffu, b.w, 1);
            if (lane == 31) {
                if (lastq) { cr = c.w; br = b.w; }          // col W-1 substitutions
                else       { cr = cur[j0 + 4]; br = nxt[j0 + 4]; }
            }
            if (lane == 0)
                bl = firstq ? b.x : nxt[j0 - 1];            // col 0 substitution

            quad_fast(c, b, bl, cr, br, acc2);

            if (i == 0) {   // row-0 horizontal pairs count double
                ull d;
                d = sub2(pk(c.x, c.y), pk(c.y, c.z)); acc2 = fma2(d, d, acc2);
                d = sub2(pk(c.z, c.w), pk(c.w, cr));  acc2 = fma2(d, d, acc2);
            }
        } else {
            // row H-1: horizontal pairs only, counted double
            const float4 c = *(const float4*)(cur + j0);
            float cr = __shfl_down_sync(0xffffffffu, c.x, 1);
            if (lane == 31) cr = lastq ? c.w : cur[j0 + 4];
            const ull vp01 = pk(c.x, c.y), vp23 = pk(c.z, c.w);
            ull d;
            d = sub2(vp01, pk(c.y, c.z));
            acc2 = fma2(d, d, acc2); acc2 = fma2(d, d, acc2);
            d = sub2(vp23, pk(c.w, cr));
            acc2 = fma2(d, d, acc2); acc2 = fma2(d, d, acc2);
        }
    }

    float lo, hi; unpk(acc2, lo, hi);
    float acc = lo + hi;

    // ---- deterministic block reduction ----
    __shared__ float swarp[NTHREADS / 32];
    #pragma unroll
    for (int o = 16; o > 0; o >>= 1)
        acc += __shfl_down_sync(0xffffffffu, acc, o);
    if ((threadIdx.x & 31) == 0) swarp[threadIdx.x >> 5] = acc;
    __syncthreads();
    if (threadIdx.x < NTHREADS / 32) {
        float v = swarp[threadIdx.x];
        #pragma unroll
        for (int o = NTHREADS / 64; o > 0; o >>= 1)
            v += __shfl_down_sync(0xffu, v, o);
        if (threadIdx.x == 0) g_part[blockIdx.x] = v;
    }

    // ---- last-block final reduction ----
    __shared__ bool isLast;
    if (threadIdx.x == 0) {
        __threadfence();
        isLast = (atomicAdd(&g_count, 1u) == (unsigned)gridDim.x - 1u);
    }
    __syncthreads();
    if (isLast) {
        volatile float* gp = g_part;
        double v = 0.0;
        for (int idx = threadIdx.x; idx < NBLOCKS; idx += NTHREADS) v += (double)gp[idx];
        __shared__ double sd[NTHREADS];
        sd[threadIdx.x] = v;
        __syncthreads();
        #pragma unroll
        for (int o = NTHREADS / 2; o > 0; o >>= 1) {
            if (threadIdx.x < o) sd[threadIdx.x] += sd[threadIdx.x + o];
            __syncthreads();
        }
        if (threadIdx.x == 0) {
            out[0] = (float)(2.0 * sd[0]);
            g_count = 0;
        }
    }
}

extern "C" void kernel_launch(void* const* d_in, const int* in_sizes, int n_in,
                              void* d_out, int out_size) {
    const float* f = (const float*)d_in[0];
    const int n = in_sizes[0];
    const int total_q = n >> 2;
    lap_kernel<<<NBLOCKS, NTHREADS>>>(f, (float*)d_out, total_q);
}